// round 15
// baseline (speedup 1.0000x reference)
#include <cuda_runtime.h>
#include <cuda_fp16.h>
#include <cstdint>

#define B_    8
#define CIN   64
#define H_    128
#define W_    128
#define COUT  128
#define HO    131
#define WO    131
#define PLANE (HO * WO)          // 17161
#define NPLANES (B_ * COUT)      // 1024

// ---------------- device scratch ----------------
__device__ __align__(16) __half  g_y [B_ * COUT * H_ * W_];  // conv out, fp16
__device__ __align__(16) __half  g_Xh[B_ * H_ * W_ * CIN];   // NHWC fp16
__device__ __align__(16) __half  g_Wh[9 * COUT * CIN];       // [tap][oc][ic] fp16

// ---------------- helpers ----------------
__device__ __forceinline__ uint32_t smem_u32(const void* p) {
    uint32_t a;
    asm("{ .reg .u64 t; cvta.to.shared.u64 t, %1; cvt.u32.u64 %0, t; }" : "=r"(a) : "l"(p));
    return a;
}
__device__ __forceinline__ void cp16(uint32_t dst, const void* src) {
    asm volatile("cp.async.cg.shared.global [%0], [%1], 16;" :: "r"(dst), "l"(src));
}
#define CP_COMMIT() asm volatile("cp.async.commit_group;" ::: "memory")
#define CP_WAIT1()  asm volatile("cp.async.wait_group 1;" ::: "memory")

__device__ __forceinline__ void ldmx4(uint32_t addr, uint32_t& r0, uint32_t& r1,
                                      uint32_t& r2, uint32_t& r3) {
    asm volatile("ldmatrix.sync.aligned.m8n8.x4.shared.b16 {%0,%1,%2,%3}, [%4];"
                 : "=r"(r0), "=r"(r1), "=r"(r2), "=r"(r3) : "r"(addr));
}
__device__ __forceinline__ void mma16816(float* c, const uint32_t* a, uint32_t b0, uint32_t b1) {
    asm volatile(
        "mma.sync.aligned.m16n8k16.row.col.f32.f16.f16.f32 "
        "{%0,%1,%2,%3}, {%4,%5,%6,%7}, {%8,%9}, {%0,%1,%2,%3};"
        : "+f"(c[0]), "+f"(c[1]), "+f"(c[2]), "+f"(c[3])
        : "r"(a[0]), "r"(a[1]), "r"(a[2]), "r"(a[3]), "r"(b0), "r"(b1));
}
// packed f32x2
__device__ __forceinline__ unsigned long long pack2(float lo, float hi) {
    unsigned long long r;
    asm("mov.b64 %0, {%1, %2};" : "=l"(r) : "f"(lo), "f"(hi));
    return r;
}
__device__ __forceinline__ void unpack2(unsigned long long v, float& lo, float& hi) {
    asm("mov.b64 {%0, %1}, %2;" : "=f"(lo), "=f"(hi) : "l"(v));
}
__device__ __forceinline__ unsigned long long fma2(unsigned long long a, unsigned long long b,
                                                   unsigned long long c) {
    unsigned long long d;
    asm("fma.rn.f32x2 %0, %1, %2, %3;" : "=l"(d) : "l"(a), "l"(b), "l"(c));
    return d;
}
__device__ __forceinline__ float fast_silu(float a) {
    return __fdividef(a, 1.f + __expf(-a));
}
__device__ __forceinline__ uint32_t h2_bits(__half2 h) {
    uint32_t u;
    memcpy(&u, &h, 4);
    return u;
}

// ---------------- conv SMEM layout (bytes) ----------------
#define XBUF(b)   ((b) * 19008)
#define WBUF(b)   (38016 + (b) * 18432)
#define SM_TOTAL  74880

__global__ void dummy_kernel() {}

// ---------------- prep kernel (x transpose + W convert fused) ----------------
__global__ __launch_bounds__(256) void prep_x_kernel(const float* __restrict__ x,
                                                     const float* __restrict__ W_in) {
    __shared__ float s[W_ * 68];
    const int y = blockIdx.x, b = blockIdx.y, tid = threadIdx.x;

    // phase 1: coalesced fp32 rows -> transposed smem
#pragma unroll
    for (int i = 0; i < 8; ++i) {
        int e  = tid + i * 256;              // 0..2047
        int ic = e >> 5;
        int p4 = (e & 31) * 4;
        float4 v = *(const float4*)&x[(((size_t)b * CIN + ic) * H_ + y) * W_ + p4];
        s[(p4 + 0) * 68 + ic] = v.x;
        s[(p4 + 1) * 68 + ic] = v.y;
        s[(p4 + 2) * 68 + ic] = v.z;
        s[(p4 + 3) * 68 + ic] = v.w;
    }
    __syncthreads();

    // phase 2: vector read + cvt + vector fp16 store
    size_t obase = ((size_t)(b * H_ + y) * W_) * CIN;
#pragma unroll
    for (int i = 0; i < 4; ++i) {
        int e   = tid + i * 256;             // 0..1023
        int px  = e >> 3;
        int ic8 = (e & 7) * 8;
        float4 a = *(const float4*)&s[px * 68 + ic8];
        float4 c = *(const float4*)&s[px * 68 + ic8 + 4];
        uint4 o;
        o.x = h2_bits(__floats2half2_rn(a.x, a.y));
        o.y = h2_bits(__floats2half2_rn(a.z, a.w));
        o.z = h2_bits(__floats2half2_rn(c.x, c.y));
        o.w = h2_bits(__floats2half2_rn(c.z, c.w));
        *(uint4*)&g_Xh[obase + (size_t)px * CIN + ic8] = o;
    }

    // fused prep_w: 9 blocks also convert one weight tap each
    if (b == 0 && blockIdx.x < 9 && tid < 128) {
        int tap = blockIdx.x, oc = tid;
        for (int ic = 0; ic < CIN; ++ic) {
            float v = W_in[(size_t)((128 + oc) * CIN + ic) * 9 + tap];
            g_Wh[(tap * COUT + oc) * CIN + ic] = __float2half(v);
        }
    }
}

// ---------------- Stage 1: implicit-GEMM conv3x3 (unchanged) ----------------
__device__ __forceinline__ void issue_xrow(uint32_t sb_x, char* sm, int xoff,
                                           int b, int row, int tid) {
    if ((unsigned)row < (unsigned)H_) {
        const char* src = (const char*)g_Xh + ((size_t)(b * H_ + row) * W_) * CIN * 2;
#pragma unroll
        for (int i = 0; i < 2; ++i) {
            int e = tid + i * 512;
            int r = e >> 3, c = e & 7;
            cp16(sb_x + (uint32_t)(r + 1) * 144 + c * 16, src + (size_t)r * 128 + c * 16);
        }
    } else {
        for (int i = 0; i < 8; ++i) {
            int e = tid + i * 512;
            int r = e >> 5, c = e & 31;
            *(uint32_t*)(sm + xoff + (r + 1) * 144 + c * 4) = 0u;
        }
    }
}

__device__ __forceinline__ void issue_w(uint32_t sb_w, int tap, int tid) {
#pragma unroll
    for (int i = 0; i < 2; ++i) {
        int e = tid + i * 512;
        int oc = e >> 3, c = e & 7;
        cp16(sb_w + (uint32_t)oc * 144 + c * 16,
             (const char*)g_Wh + ((size_t)tap * COUT + oc) * 128 + c * 16);
    }
}

__global__ __launch_bounds__(512, 2)
void conv3x3_mma_kernel() {
    extern __shared__ char sm[];
    const uint32_t sbase = smem_u32(sm);
    const int tid = threadIdx.x;
    const int b   = blockIdx.x >> 7;
    const int y   = blockIdx.x & 127;

    const int wid = tid >> 5, l = tid & 31;
    const int mrow0 = (wid & 3) * 32;
    const int ncol0 = (wid >> 2) * 32;
    const uint32_t frag_off = (uint32_t)(l & 15) * 144 + (uint32_t)(l >> 4) * 16;

    if (tid < 128) {
        int buf  = tid >> 6;
        int rem  = tid & 63;
        int slot = (rem >= 32) ? 129 : 0;
        int c    = rem & 31;
        *(uint32_t*)(sm + XBUF(buf) + slot * 144 + c * 4) = 0u;
    }

    float acc[2][4][4];
#pragma unroll
    for (int mt = 0; mt < 2; ++mt)
#pragma unroll
        for (int nt = 0; nt < 4; ++nt)
#pragma unroll
            for (int j = 0; j < 4; ++j) acc[mt][nt][j] = 0.f;

    issue_xrow(sbase + XBUF(0), sm, XBUF(0), b, y - 1, tid);
    issue_w(sbase + WBUF(0), 0, tid);
    CP_COMMIT();
    issue_xrow(sbase + XBUF(1), sm, XBUF(1), b, y, tid);
    issue_w(sbase + WBUF(1), 1, tid);
    CP_COMMIT();

    for (int t = 0; t < 9; ++t) {
        const int ky = (t >= 6) ? 2 : (t >= 3 ? 1 : 0);
        const int kx = t - 3 * ky;
        CP_WAIT1();
        __syncthreads();

        const uint32_t aB = sbase + WBUF(t & 1) + (uint32_t)mrow0 * 144 + frag_off;
        const uint32_t bB = sbase + XBUF(ky & 1) + (uint32_t)(kx + ncol0) * 144 + frag_off;

#pragma unroll
        for (int kk = 0; kk < 4; ++kk) {
            uint32_t a[8];
#pragma unroll
            for (int mtt = 0; mtt < 2; ++mtt)
                ldmx4(aB + (uint32_t)mtt * 16 * 144 + kk * 32,
                      a[mtt * 4 + 0], a[mtt * 4 + 1], a[mtt * 4 + 2], a[mtt * 4 + 3]);
            uint32_t bf[4][2];
#pragma unroll
            for (int nb = 0; nb < 2; ++nb) {
                uint32_t r0, r1, r2, r3;
                ldmx4(bB + (uint32_t)nb * 16 * 144 + kk * 32, r0, r1, r2, r3);
                bf[nb * 2 + 0][0] = r0; bf[nb * 2 + 0][1] = r2;
                bf[nb * 2 + 1][0] = r1; bf[nb * 2 + 1][1] = r3;
            }
#pragma unroll
            for (int mt = 0; mt < 2; ++mt)
#pragma unroll
                for (int nt = 0; nt < 4; ++nt)
                    mma16816(acc[mt][nt], a + mt * 4, bf[nt][0], bf[nt][1]);
        }
        __syncthreads();
        if (t < 8) {
            if (t + 2 <= 8) issue_w(sbase + WBUF(t & 1), t + 2, tid);
            if (t == 3)     issue_xrow(sbase + XBUF(0), sm, XBUF(0), b, y + 1, tid);
            CP_COMMIT();
        }
    }

    __half* yb = g_y + (size_t)b * COUT * H_ * W_;
#pragma unroll
    for (int mt = 0; mt < 2; ++mt) {
#pragma unroll
        for (int nt = 0; nt < 4; ++nt) {
            int r   = mrow0 + mt * 16 + (l >> 2);
            int col = ncol0 + nt * 8 + (l & 3) * 2;
            *(__half2*)&yb[((size_t)r * H_ + y) * W_ + col]
                = __floats2half2_rn(acc[mt][nt][0], acc[mt][nt][1]);
            *(__half2*)&yb[((size_t)(r + 8) * H_ + y) * W_ + col]
                = __floats2half2_rn(acc[mt][nt][2], acc[mt][nt][3]);
        }
    }
}

// ---------------- Stage 2+3 fused: dwconv4x4 + silu + head matmul ----------------
// smem: Xs half[128*140+8] (stride 140, data i at position 4+i) | xh | Wsm
#define XS_HALVES  (128 * 140 + 8)
#define XS_BYTES   (XS_HALVES * 2)                 // 35856
#define XH_OFF     XS_BYTES
#define WSM_OFF    (XH_OFF + 17192 * 2)            // 70240
#define DW_SM_TOTAL (WSM_OFF + 32 * 80)            // 72800 -> 3 CTAs/SM

__global__ __launch_bounds__(512, 3)
void dwhead_kernel(const float* __restrict__ Wc, const float* __restrict__ bc,
                   const float* __restrict__ W_out, float* __restrict__ out) {
    extern __shared__ char sm[];
    __half* Xs  = (__half*)sm;
    __half* xh  = (__half*)(sm + XH_OFF);
    __half* Wsm = (__half*)(sm + WSM_OFF);

    const int tid = threadIdx.x;
    const int P   = blockIdx.x;
    const int c   = P & 127;
    const int lane = tid & 31, wid = tid >> 5;

    const long base    = (long)P * PLANE;
    const int g_start  = (int)((base + 31) >> 5);
    const int g_end    = (int)((base + PLANE + 31) >> 5);
    const int s0       = (int)((long)g_start * 32 - base);
    const int n_groups = g_end - g_start;
    const int n_k      = n_groups * 32;

    // dw weights duplicated as f32x2 + bias
    unsigned long long w2[16];
#pragma unroll
    for (int i = 0; i < 16; ++i) {
        float wv = Wc[c * 16 + i];
        w2[i] = pack2(wv, wv);
    }
    const float bias = bc[c];
    const unsigned long long bias2 = pack2(bias, bias);

    // stage W_out -> smem fp16
    for (int i = tid; i < 1024; i += 512) {
        int e = i >> 5, d = i & 31;
        Wsm[e * 40 + d] = __float2half(W_out[i]);
    }

    // plane load: LDG.128 + 2x STS.64, data i -> position 4+i, stride 140
    const uint4* gy4 = (const uint4*)(g_y + (size_t)P * (H_ * W_));
#pragma unroll
    for (int i = 0; i < 4; ++i) {
        int idx = tid + i * 512;                   // 0..2047
        uint4 v = gy4[idx];
        int r  = idx >> 4;
        int c8 = (idx & 15) * 8;
        *(uint2*)&Xs[r * 140 + 4 + c8]     = make_uint2(v.x, v.y);
        *(uint2*)&Xs[r * 140 + 8 + c8]     = make_uint2(v.z, v.w);
    }
    // halos: positions 1..3 (i=-3..-1) and 132..135 per row
    for (int idx = tid; idx < 896; idx += 512) {
        int r = idx / 7, t = idx - r * 7;
        int col = (t < 3) ? (1 + t) : (129 + t);   // 1,2,3,132,133,134,135
        Xs[r * 140 + col] = __float2half(0.f);
    }
    __syncthreads();

    // phase A: dwconv + silu -> xh, f32x2 packed
    const int nitem = HO * 33;
    for (int it = tid; it < nitem; it += 512) {
        int y  = it / 33;
        int j  = it - y * 33;
        int x0 = j * 4;
        unsigned long long A01 = bias2, A23 = bias2;
#pragma unroll
        for (int ky = 0; ky < 4; ++ky) {
            int r = y - 3 + ky;
            if ((unsigned)r < 128u) {
                const __half* xr = &Xs[r * 140 + x0];
                uint2 qa = *(const uint2*)xr;          // positions x0..x0+3
                uint2 qb = *(const uint2*)(xr + 4);    // positions x0+4..x0+7
                float2 f0 = __half22float2(*(__half2*)&qa.x);
                float2 f1 = __half22float2(*(__half2*)&qa.y);
                float2 f2 = __half22float2(*(__half2*)&qb.x);
                float2 f3 = __half22float2(*(__half2*)&qb.y);
                unsigned long long p1 = pack2(f0.y, f1.x);
                unsigned long long p2 = pack2(f1.x, f1.y);
                unsigned long long p3 = pack2(f1.y, f2.x);
                unsigned long long p4 = pack2(f2.x, f2.y);
                unsigned long long p5 = pack2(f2.y, f3.x);
                unsigned long long p6 = pack2(f3.x, f3.y);
                const unsigned long long* wk = w2 + ky * 4;
                A01 = fma2(p1, wk[0], A01);
                A01 = fma2(p2, wk[1], A01);
                A01 = fma2(p3, wk[2], A01);
                A01 = fma2(p4, wk[3], A01);
                A23 = fma2(p3, wk[0], A23);
                A23 = fma2(p4, wk[1], A23);
                A23 = fma2(p5, wk[2], A23);
                A23 = fma2(p6, wk[3], A23);
            }
        }
        float a0, a1, a2, a3;
        unpack2(A01, a0, a1);
        unpack2(A23, a2, a3);
        float sv[4] = { fast_silu(a0), fast_silu(a1), fast_silu(a2), fast_silu(a3) };
#pragma unroll
        for (int o = 0; o < 4; ++o) {
            int x = x0 + o;
            if (x < WO) {
                int k = y * WO + x - s0;
                if (k >= 0) xh[k] = __float2half(sv[o]);
            }
        }
    }

    // straddle: first <=31 outputs of next plane (row 0, ky=3 only)
    if (P < NPLANES - 1 && tid < 31) {
        int i = tid;
        int k = PLANE + i - s0;
        if (k < n_k) {
            int cn = (P + 1) & 127;
            float acc = bc[cn];
            const __half* gp = g_y + (size_t)(P + 1) * (H_ * W_);
#pragma unroll
            for (int kx = 0; kx < 4; ++kx) {
                int ci = i - 3 + kx;
                if (ci >= 0) acc += __half2float(gp[ci]) * Wc[cn * 16 + 12 + kx];
            }
            xh[k] = __float2half(fast_silu(acc));
        }
    }
    __syncthreads();

    // phase B: head matmul via mma (mt-outer)
    const uint32_t wb = smem_u32(Wsm);
    const uint32_t xb = smem_u32(xh);
    const uint32_t foW = (uint32_t)(lane & 15) * 80 + (uint32_t)(lane >> 4) * 16;
    const uint32_t foX = (uint32_t)(lane & 15) * 64 + (uint32_t)(lane >> 4) * 16;
    const int n_tiles = (n_groups + 15) >> 4;

#pragma unroll
    for (int mt = 0; mt < 2; ++mt) {
        uint32_t afr[2][4];
#pragma unroll
        for (int kk = 0; kk < 2; ++kk)
            ldmx4(wb + (uint32_t)mt * 16 * 80 + kk * 32 + foW,
                  afr[kk][0], afr[kk][1], afr[kk][2], afr[kk][3]);

        for (int j = wid; j < n_tiles; j += 16) {
            uint32_t tb = xb + (uint32_t)j * 16 * 64 + foX;
            uint32_t b0[2][2], b1[2][2];
            {
                uint32_t r0, r1, r2, r3;
                ldmx4(tb,      r0, r1, r2, r3);
                b0[0][0] = r0; b0[0][1] = r2;
                b0[1][0] = r1; b0[1][1] = r3;
                ldmx4(tb + 32, r0, r1, r2, r3);
                b1[0][0] = r0; b1[0][1] = r2;
                b1[1][0] = r1; b1[1][1] = r3;
            }
#pragma unroll
            for (int nt = 0; nt < 2; ++nt) {
                float cfr[4] = { 0.f, 0.f, 0.f, 0.f };
                mma16816(cfr, afr[0], b0[nt][0], b0[nt][1]);
                mma16816(cfr, afr[1], b1[nt][0], b1[nt][1]);
                int e  = mt * 16 + (lane >> 2);
                int g0 = j * 16 + nt * 8 + (lane & 3) * 2;
                if (g0 < n_groups) {
                    float* o = out + (size_t)(g_start + g0) * 32;
                    o[e]     = cfr[0];
                    o[e + 8] = cfr[2];
                }
                if (g0 + 1 < n_groups) {
                    float* o = out + (size_t)(g_start + g0 + 1) * 32;
                    o[e]     = cfr[1];
                    o[e + 8] = cfr[3];
                }
            }
        }
    }
}

// ---------------- launch ----------------
extern "C" void kernel_launch(void* const* d_in, const int* in_sizes, int n_in,
                              void* d_out, int out_size) {
    const float* x      = (const float*)d_in[0];
    const float* W_in   = (const float*)d_in[1];
    const float* W_conv = (const float*)d_in[2];
    const float* b_conv = (const float*)d_in[3];
    const float* W_out  = (const float*)d_in[7];
    float* out = (float*)d_out;

    cudaFuncSetAttribute(conv3x3_mma_kernel,
                         cudaFuncAttributeMaxDynamicSharedMemorySize, SM_TOTAL);
    cudaFuncSetAttribute(dwhead_kernel,
                         cudaFuncAttributeMaxDynamicSharedMemorySize, DW_SM_TOTAL);

    dummy_kernel<<<1, 32>>>();                         // keeps dwhead at ncu index 3
    prep_x_kernel<<<dim3(H_, B_), 256>>>(x, W_in);
    conv3x3_mma_kernel<<<B_ * H_, 512, SM_TOTAL>>>();
    dwhead_kernel<<<NPLANES, 512, DW_SM_TOTAL>>>(W_conv, b_conv, W_out, out);
}

// round 16
// speedup vs baseline: 1.0127x; 1.0127x over previous
#include <cuda_runtime.h>
#include <cuda_fp16.h>
#include <cstdint>

#define B_    8
#define CIN   64
#define H_    128
#define W_    128
#define COUT  128
#define HO    131
#define WO    131
#define PLANE (HO * WO)          // 17161
#define NPLANES (B_ * COUT)      // 1024

// ---------------- device scratch ----------------
__device__ __align__(16) __half  g_y [B_ * COUT * H_ * W_];  // conv out, fp16
__device__ __align__(16) __half  g_Xh[B_ * H_ * W_ * CIN];   // NHWC fp16
__device__ __align__(16) __half  g_Wh[9 * COUT * CIN];       // [tap][oc][ic] fp16

// ---------------- helpers ----------------
__device__ __forceinline__ uint32_t smem_u32(const void* p) {
    uint32_t a;
    asm("{ .reg .u64 t; cvta.to.shared.u64 t, %1; cvt.u32.u64 %0, t; }" : "=r"(a) : "l"(p));
    return a;
}
__device__ __forceinline__ void cp16(uint32_t dst, const void* src) {
    asm volatile("cp.async.cg.shared.global [%0], [%1], 16;" :: "r"(dst), "l"(src));
}
#define CP_COMMIT() asm volatile("cp.async.commit_group;" ::: "memory")
#define CP_WAIT1()  asm volatile("cp.async.wait_group 1;" ::: "memory")

__device__ __forceinline__ void ldmx4(uint32_t addr, uint32_t& r0, uint32_t& r1,
                                      uint32_t& r2, uint32_t& r3) {
    asm volatile("ldmatrix.sync.aligned.m8n8.x4.shared.b16 {%0,%1,%2,%3}, [%4];"
                 : "=r"(r0), "=r"(r1), "=r"(r2), "=r"(r3) : "r"(addr));
}
__device__ __forceinline__ void mma16816(float* c, const uint32_t* a, uint32_t b0, uint32_t b1) {
    asm volatile(
        "mma.sync.aligned.m16n8k16.row.col.f32.f16.f16.f32 "
        "{%0,%1,%2,%3}, {%4,%5,%6,%7}, {%8,%9}, {%0,%1,%2,%3};"
        : "+f"(c[0]), "+f"(c[1]), "+f"(c[2]), "+f"(c[3])
        : "r"(a[0]), "r"(a[1]), "r"(a[2]), "r"(a[3]), "r"(b0), "r"(b1));
}
__device__ __forceinline__ float fast_silu(float a) {
    return __fdividef(a, 1.f + __expf(-a));
}
__device__ __forceinline__ uint32_t h2_bits(__half2 h) {
    uint32_t u;
    memcpy(&u, &h, 4);
    return u;
}

// ---------------- conv SMEM layout (bytes) ----------------
#define XBUF(b)   ((b) * 19008)
#define WBUF(b)   (38016 + (b) * 18432)
#define SM_TOTAL  74880

// ---------------- prep kernel (x transpose + W convert fused) ----------------
__global__ __launch_bounds__(256) void prep_x_kernel(const float* __restrict__ x,
                                                     const float* __restrict__ W_in) {
    __shared__ float s[W_ * 68];
    const int y = blockIdx.x, b = blockIdx.y, tid = threadIdx.x;

    // phase 1: coalesced fp32 rows -> transposed smem
#pragma unroll
    for (int i = 0; i < 8; ++i) {
        int e  = tid + i * 256;              // 0..2047
        int ic = e >> 5;
        int p4 = (e & 31) * 4;
        float4 v = *(const float4*)&x[(((size_t)b * CIN + ic) * H_ + y) * W_ + p4];
        s[(p4 + 0) * 68 + ic] = v.x;
        s[(p4 + 1) * 68 + ic] = v.y;
        s[(p4 + 2) * 68 + ic] = v.z;
        s[(p4 + 3) * 68 + ic] = v.w;
    }
    __syncthreads();

    // phase 2: vector read + cvt + vector fp16 store
    size_t obase = ((size_t)(b * H_ + y) * W_) * CIN;
#pragma unroll
    for (int i = 0; i < 4; ++i) {
        int e   = tid + i * 256;             // 0..1023
        int px  = e >> 3;
        int ic8 = (e & 7) * 8;
        float4 a = *(const float4*)&s[px * 68 + ic8];
        float4 c = *(const float4*)&s[px * 68 + ic8 + 4];
        uint4 o;
        o.x = h2_bits(__floats2half2_rn(a.x, a.y));
        o.y = h2_bits(__floats2half2_rn(a.z, a.w));
        o.z = h2_bits(__floats2half2_rn(c.x, c.y));
        o.w = h2_bits(__floats2half2_rn(c.z, c.w));
        *(uint4*)&g_Xh[obase + (size_t)px * CIN + ic8] = o;
    }

    // fused prep_w: 9 blocks also convert one weight tap each
    if (b == 0 && blockIdx.x < 9 && tid < 128) {
        int tap = blockIdx.x, oc = tid;
        for (int ic = 0; ic < CIN; ++ic) {
            float v = W_in[(size_t)((128 + oc) * CIN + ic) * 9 + tap];
            g_Wh[(tap * COUT + oc) * CIN + ic] = __float2half(v);
        }
    }
}

// ---------------- Stage 1: implicit-GEMM conv3x3 (proven ~72us) ----------------
__device__ __forceinline__ void issue_xrow(uint32_t sb_x, char* sm, int xoff,
                                           int b, int row, int tid) {
    if ((unsigned)row < (unsigned)H_) {
        const char* src = (const char*)g_Xh + ((size_t)(b * H_ + row) * W_) * CIN * 2;
#pragma unroll
        for (int i = 0; i < 2; ++i) {
            int e = tid + i * 512;
            int r = e >> 3, c = e & 7;
            cp16(sb_x + (uint32_t)(r + 1) * 144 + c * 16, src + (size_t)r * 128 + c * 16);
        }
    } else {
        for (int i = 0; i < 8; ++i) {
            int e = tid + i * 512;
            int r = e >> 5, c = e & 31;
            *(uint32_t*)(sm + xoff + (r + 1) * 144 + c * 4) = 0u;
        }
    }
}

__device__ __forceinline__ void issue_w(uint32_t sb_w, int tap, int tid) {
#pragma unroll
    for (int i = 0; i < 2; ++i) {
        int e = tid + i * 512;
        int oc = e >> 3, c = e & 7;
        cp16(sb_w + (uint32_t)oc * 144 + c * 16,
             (const char*)g_Wh + ((size_t)tap * COUT + oc) * 128 + c * 16);
    }
}

__global__ __launch_bounds__(512, 2)
void conv3x3_mma_kernel() {
    extern __shared__ char sm[];
    const uint32_t sbase = smem_u32(sm);
    const int tid = threadIdx.x;
    const int b   = blockIdx.x >> 7;
    const int y   = blockIdx.x & 127;

    const int wid = tid >> 5, l = tid & 31;
    const int mrow0 = (wid & 3) * 32;
    const int ncol0 = (wid >> 2) * 32;
    const uint32_t frag_off = (uint32_t)(l & 15) * 144 + (uint32_t)(l >> 4) * 16;

    if (tid < 128) {
        int buf  = tid >> 6;
        int rem  = tid & 63;
        int slot = (rem >= 32) ? 129 : 0;
        int c    = rem & 31;
        *(uint32_t*)(sm + XBUF(buf) + slot * 144 + c * 4) = 0u;
    }

    float acc[2][4][4];
#pragma unroll
    for (int mt = 0; mt < 2; ++mt)
#pragma unroll
        for (int nt = 0; nt < 4; ++nt)
#pragma unroll
            for (int j = 0; j < 4; ++j) acc[mt][nt][j] = 0.f;

    issue_xrow(sbase + XBUF(0), sm, XBUF(0), b, y - 1, tid);
    issue_w(sbase + WBUF(0), 0, tid);
    CP_COMMIT();
    issue_xrow(sbase + XBUF(1), sm, XBUF(1), b, y, tid);
    issue_w(sbase + WBUF(1), 1, tid);
    CP_COMMIT();

    for (int t = 0; t < 9; ++t) {
        const int ky = (t >= 6) ? 2 : (t >= 3 ? 1 : 0);
        const int kx = t - 3 * ky;
        CP_WAIT1();
        __syncthreads();

        const uint32_t aB = sbase + WBUF(t & 1) + (uint32_t)mrow0 * 144 + frag_off;
        const uint32_t bB = sbase + XBUF(ky & 1) + (uint32_t)(kx + ncol0) * 144 + frag_off;

#pragma unroll
        for (int kk = 0; kk < 4; ++kk) {
            uint32_t a[8];
#pragma unroll
            for (int mtt = 0; mtt < 2; ++mtt)
                ldmx4(aB + (uint32_t)mtt * 16 * 144 + kk * 32,
                      a[mtt * 4 + 0], a[mtt * 4 + 1], a[mtt * 4 + 2], a[mtt * 4 + 3]);
            uint32_t bf[4][2];
#pragma unroll
            for (int nb = 0; nb < 2; ++nb) {
                uint32_t r0, r1, r2, r3;
                ldmx4(bB + (uint32_t)nb * 16 * 144 + kk * 32, r0, r1, r2, r3);
                bf[nb * 2 + 0][0] = r0; bf[nb * 2 + 0][1] = r2;
                bf[nb * 2 + 1][0] = r1; bf[nb * 2 + 1][1] = r3;
            }
#pragma unroll
            for (int mt = 0; mt < 2; ++mt)
#pragma unroll
                for (int nt = 0; nt < 4; ++nt)
                    mma16816(acc[mt][nt], a + mt * 4, bf[nt][0], bf[nt][1]);
        }
        __syncthreads();
        if (t < 8) {
            if (t + 2 <= 8) issue_w(sbase + WBUF(t & 1), t + 2, tid);
            if (t == 3)     issue_xrow(sbase + XBUF(0), sm, XBUF(0), b, y + 1, tid);
            CP_COMMIT();
        }
    }

    __half* yb = g_y + (size_t)b * COUT * H_ * W_;
#pragma unroll
    for (int mt = 0; mt < 2; ++mt) {
#pragma unroll
        for (int nt = 0; nt < 4; ++nt) {
            int r   = mrow0 + mt * 16 + (l >> 2);
            int col = ncol0 + nt * 8 + (l & 3) * 2;
            *(__half2*)&yb[((size_t)r * H_ + y) * W_ + col]
                = __floats2half2_rn(acc[mt][nt][0], acc[mt][nt][1]);
            *(__half2*)&yb[((size_t)(r + 8) * H_ + y) * W_ + col]
                = __floats2half2_rn(acc[mt][nt][2], acc[mt][nt][3]);
        }
    }
}

// ---------------- Stage 2+3 fused: dwconv4x4 + silu + head matmul ----------------
// R12 layout (proven 63.07us): Xs half[128*136+16] | xh half[17192] | Wsm half[32x40]
#define XS_BYTES   ((128 * 136 + 16) * 2)          // 34848
#define XH_OFF     XS_BYTES
#define WSM_OFF    (XH_OFF + 17192 * 2)            // 69232
#define DW_SM_TOTAL (WSM_OFF + 32 * 80)            // 71792 -> 3 CTAs/SM

__global__ __launch_bounds__(512, 3)
void dwhead_kernel(const float* __restrict__ Wc, const float* __restrict__ bc,
                   const float* __restrict__ W_out, float* __restrict__ out) {
    extern __shared__ char sm[];
    __half* Xs  = (__half*)sm;
    __half* xh  = (__half*)(sm + XH_OFF);
    __half* Wsm = (__half*)(sm + WSM_OFF);

    const int tid = threadIdx.x;
    const int P   = blockIdx.x;
    const int c   = P & 127;
    const int lane = tid & 31, wid = tid >> 5;

    const long base    = (long)P * PLANE;
    const int g_start  = (int)((base + 31) >> 5);
    const int g_end    = (int)((base + PLANE + 31) >> 5);
    const int s0       = (int)((long)g_start * 32 - base);
    const int n_groups = g_end - g_start;
    const int n_k      = n_groups * 32;

    float w[16];
#pragma unroll
    for (int i = 0; i < 16; ++i) w[i] = Wc[c * 16 + i];
    const float bias = bc[c];

    // ---- stage W_out -> smem fp16 ----
    for (int i = tid; i < 1024; i += 512) {
        int e = i >> 5, d = i & 31;
        Wsm[e * 40 + d] = __float2half(W_out[i]);
    }

    // ---- plane load (fp16, vector LDG + scalar STS) ----
    const uint4* gy4 = (const uint4*)(g_y + (size_t)P * (H_ * W_));
#pragma unroll
    for (int i = 0; i < 4; ++i) {
        int idx = tid + i * 512;                   // 0..2047
        uint4 v = gy4[idx];
        int r  = idx >> 4;                          // 16 uint4 per 128-half row
        int c8 = (idx & 15) * 8;
        __half* dst = &Xs[r * 136 + 3 + c8];
        const __half* sv = (const __half*)&v;
#pragma unroll
        for (int t2 = 0; t2 < 8; ++t2) dst[t2] = sv[t2];
    }
    // halos: idx 0..2 and 131..135 per row, + pad tail
    for (int idx = tid; idx < 1024; idx += 512) {
        int r = idx >> 3, cc = idx & 7;
        int col = (cc < 3) ? cc : (128 + cc);      // 0,1,2,131..135
        Xs[r * 136 + col] = __float2half(0.f);
    }
    if (tid < 16) Xs[128 * 136 + tid] = __float2half(0.f);
    __syncthreads();

    // ---- phase A: dwconv + silu -> xh (R12 scalar, proven) ----
    const int nitem = HO * 33;
    for (int it = tid; it < nitem; it += 512) {
        int y  = it / 33;
        int j  = it - y * 33;
        int x0 = j * 4;
        float a[4] = { bias, bias, bias, bias };
#pragma unroll
        for (int ky = 0; ky < 4; ++ky) {
            int r = y - 3 + ky;
            if ((unsigned)r < 128u) {
                const __half* xr = &Xs[r * 136 + x0];
                uint2 qa = *(const uint2*)xr;
                uint2 qb = *(const uint2*)(xr + 4);
                float2 f0 = __half22float2(*(__half2*)&qa.x);
                float2 f1 = __half22float2(*(__half2*)&qa.y);
                float2 f2 = __half22float2(*(__half2*)&qb.x);
                float2 f3 = __half22float2(*(__half2*)&qb.y);
                float xv[8] = { f0.x, f0.y, f1.x, f1.y, f2.x, f2.y, f3.x, f3.y };
                const float* wk = w + ky * 4;
#pragma unroll
                for (int o = 0; o < 4; ++o)
#pragma unroll
                    for (int kx = 0; kx < 4; ++kx)
                        a[o] += xv[o + kx] * wk[kx];
            }
        }
#pragma unroll
        for (int o = 0; o < 4; ++o) {
            int x = x0 + o;
            if (x < WO) {
                int k = y * WO + x - s0;
                if (k >= 0) xh[k] = __float2half(fast_silu(a[o]));
            }
        }
    }

    // ---- straddle: first <=31 outputs of next plane (row 0, ky=3 only) ----
    if (P < NPLANES - 1 && tid < 31) {
        int i = tid;
        int k = PLANE + i - s0;
        if (k < n_k) {
            int cn = (P + 1) & 127;
            float acc = bc[cn];
            const __half* gp = g_y + (size_t)(P + 1) * (H_ * W_);
#pragma unroll
            for (int kx = 0; kx < 4; ++kx) {
                int ci = i - 3 + kx;
                if (ci >= 0) acc += __half2float(gp[ci]) * Wc[cn * 16 + 12 + kx];
            }
            xh[k] = __float2half(fast_silu(acc));
        }
    }
    __syncthreads();

    // ---- phase B: head matmul via mma (mt-outer) ----
    const uint32_t wb = smem_u32(Wsm);
    const uint32_t xb = smem_u32(xh);
    const uint32_t foW = (uint32_t)(lane & 15) * 80 + (uint32_t)(lane >> 4) * 16;
    const uint32_t foX = (uint32_t)(lane & 15) * 64 + (uint32_t)(lane >> 4) * 16;
    const int n_tiles = (n_groups + 15) >> 4;

#pragma unroll
    for (int mt = 0; mt < 2; ++mt) {
        uint32_t afr[2][4];
#pragma unroll
        for (int kk = 0; kk < 2; ++kk)
            ldmx4(wb + (uint32_t)mt * 16 * 80 + kk * 32 + foW,
                  afr[kk][0], afr[kk][1], afr[kk][2], afr[kk][3]);

        for (int j = wid; j < n_tiles; j += 16) {
            uint32_t tb = xb + (uint32_t)j * 16 * 64 + foX;
            uint32_t b0[2][2], b1[2][2];
            {
                uint32_t r0, r1, r2, r3;
                ldmx4(tb,      r0, r1, r2, r3);
                b0[0][0] = r0; b0[0][1] = r2;
                b0[1][0] = r1; b0[1][1] = r3;
                ldmx4(tb + 32, r0, r1, r2, r3);
                b1[0][0] = r0; b1[0][1] = r2;
                b1[1][0] = r1; b1[1][1] = r3;
            }
#pragma unroll
            for (int nt = 0; nt < 2; ++nt) {
                float cfr[4] = { 0.f, 0.f, 0.f, 0.f };
                mma16816(cfr, afr[0], b0[nt][0], b0[nt][1]);
                mma16816(cfr, afr[1], b1[nt][0], b1[nt][1]);
                int e  = mt * 16 + (lane >> 2);
                int g0 = j * 16 + nt * 8 + (lane & 3) * 2;
                if (g0 < n_groups) {
                    float* o = out + (size_t)(g_start + g0) * 32;
                    o[e]     = cfr[0];
                    o[e + 8] = cfr[2];
                }
                if (g0 + 1 < n_groups) {
                    float* o = out + (size_t)(g_start + g0 + 1) * 32;
                    o[e]     = cfr[1];
                    o[e + 8] = cfr[3];
                }
            }
        }
    }
}

// ---------------- launch ----------------
extern "C" void kernel_launch(void* const* d_in, const int* in_sizes, int n_in,
                              void* d_out, int out_size) {
    const float* x      = (const float*)d_in[0];
    const float* W_in   = (const float*)d_in[1];
    const float* W_conv = (const float*)d_in[2];
    const float* b_conv = (const float*)d_in[3];
    const float* W_out  = (const float*)d_in[7];
    float* out = (float*)d_out;

    cudaFuncSetAttribute(conv3x3_mma_kernel,
                         cudaFuncAttributeMaxDynamicSharedMemorySize, SM_TOTAL);
    cudaFuncSetAttribute(dwhead_kernel,
                         cudaFuncAttributeMaxDynamicSharedMemorySize, DW_SM_TOTAL);

    prep_x_kernel<<<dim3(H_, B_), 256>>>(x, W_in);
    conv3x3_mma_kernel<<<B_ * H_, 512, SM_TOTAL>>>();
    dwhead_kernel<<<NPLANES, 512, DW_SM_TOTAL>>>(W_conv, b_conv, W_out, out);
}

// round 17
// speedup vs baseline: 1.0553x; 1.0421x over previous
#include <cuda_runtime.h>
#include <cuda_fp16.h>
#include <cstdint>

#define B_    8
#define CIN   64
#define H_    128
#define W_    128
#define COUT  128
#define HO    131
#define WO    131
#define PLANE (HO * WO)          // 17161
#define NPLANES (B_ * COUT)      // 1024

// ---------------- device scratch ----------------
__device__ __align__(16) __half  g_y [B_ * COUT * H_ * W_];  // conv out, fp16
__device__ __align__(16) __half  g_Xh[B_ * H_ * W_ * CIN];   // NHWC fp16
__device__ __align__(16) __half  g_Wh[9 * COUT * CIN];       // [tap][oc][ic] fp16

// ---------------- helpers ----------------
__device__ __forceinline__ uint32_t smem_u32(const void* p) {
    uint32_t a;
    asm("{ .reg .u64 t; cvta.to.shared.u64 t, %1; cvt.u32.u64 %0, t; }" : "=r"(a) : "l"(p));
    return a;
}
__device__ __forceinline__ void cp16(uint32_t dst, const void* src) {
    asm volatile("cp.async.cg.shared.global [%0], [%1], 16;" :: "r"(dst), "l"(src));
}
#define CP_COMMIT() asm volatile("cp.async.commit_group;" ::: "memory")
#define CP_WAIT1()  asm volatile("cp.async.wait_group 1;" ::: "memory")

__device__ __forceinline__ void ldmx4(uint32_t addr, uint32_t& r0, uint32_t& r1,
                                      uint32_t& r2, uint32_t& r3) {
    asm volatile("ldmatrix.sync.aligned.m8n8.x4.shared.b16 {%0,%1,%2,%3}, [%4];"
                 : "=r"(r0), "=r"(r1), "=r"(r2), "=r"(r3) : "r"(addr));
}
__device__ __forceinline__ void mma16816(float* c, const uint32_t* a, uint32_t b0, uint32_t b1) {
    asm volatile(
        "mma.sync.aligned.m16n8k16.row.col.f32.f16.f16.f32 "
        "{%0,%1,%2,%3}, {%4,%5,%6,%7}, {%8,%9}, {%0,%1,%2,%3};"
        : "+f"(c[0]), "+f"(c[1]), "+f"(c[2]), "+f"(c[3])
        : "r"(a[0]), "r"(a[1]), "r"(a[2]), "r"(a[3]), "r"(b0), "r"(b1));
}
__device__ __forceinline__ float fast_silu(float a) {
    return __fdividef(a, 1.f + __expf(-a));
}

// ---------------- conv SMEM layout (bytes) ----------------
#define XBUF(b)   ((b) * 19008)
#define WBUF(b)   (38016 + (b) * 18432)
#define SM_TOTAL  74880

// ---------------- prep kernel: R12 conflict-free transpose + fused W convert ----
__global__ __launch_bounds__(256) void prep_x_kernel(const float* __restrict__ x,
                                                     const float* __restrict__ W_in) {
    __shared__ float s[W_ * (CIN + 1)];
    const int y = blockIdx.x, b = blockIdx.y, tid = threadIdx.x;

    // phase 1: coalesced loads (lanes vary xx), conflict-free stores (bank = xx mod 32)
    for (int k = 0; k < 32; ++k) {
        int idx = tid + k * 256;
        int ic = idx >> 7, xx = idx & 127;
        s[xx * (CIN + 1) + ic] = x[((size_t)(b * CIN + ic) * H_ + y) * W_ + xx];
    }
    __syncthreads();

    // phase 2: conflict-free reads (lanes vary ic), coalesced fp16 stores
    size_t obase = ((size_t)(b * H_ + y) * W_) * CIN;
    for (int k = 0; k < 32; ++k) {
        int idx = tid + k * 256;
        int p = idx >> 6, ic = idx & 63;
        g_Xh[obase + (size_t)p * CIN + ic] = __float2half(s[p * (CIN + 1) + ic]);
    }

    // fused prep_w: 9 blocks also convert one weight tap each
    if (b == 0 && blockIdx.x < 9 && tid < 128) {
        int tap = blockIdx.x, oc = tid;
        for (int ic = 0; ic < CIN; ++ic) {
            float v = W_in[(size_t)((128 + oc) * CIN + ic) * 9 + tap];
            g_Wh[(tap * COUT + oc) * CIN + ic] = __float2half(v);
        }
    }
}

// ---------------- Stage 1: implicit-GEMM conv3x3 (proven ~72us) ----------------
__device__ __forceinline__ void issue_xrow(uint32_t sb_x, char* sm, int xoff,
                                           int b, int row, int tid) {
    if ((unsigned)row < (unsigned)H_) {
        const char* src = (const char*)g_Xh + ((size_t)(b * H_ + row) * W_) * CIN * 2;
#pragma unroll
        for (int i = 0; i < 2; ++i) {
            int e = tid + i * 512;
            int r = e >> 3, c = e & 7;
            cp16(sb_x + (uint32_t)(r + 1) * 144 + c * 16, src + (size_t)r * 128 + c * 16);
        }
    } else {
        for (int i = 0; i < 8; ++i) {
            int e = tid + i * 512;
            int r = e >> 5, c = e & 31;
            *(uint32_t*)(sm + xoff + (r + 1) * 144 + c * 4) = 0u;
        }
    }
}

__device__ __forceinline__ void issue_w(uint32_t sb_w, int tap, int tid) {
#pragma unroll
    for (int i = 0; i < 2; ++i) {
        int e = tid + i * 512;
        int oc = e >> 3, c = e & 7;
        cp16(sb_w + (uint32_t)oc * 144 + c * 16,
             (const char*)g_Wh + ((size_t)tap * COUT + oc) * 128 + c * 16);
    }
}

__global__ __launch_bounds__(512, 2)
void conv3x3_mma_kernel() {
    extern __shared__ char sm[];
    const uint32_t sbase = smem_u32(sm);
    const int tid = threadIdx.x;
    const int b   = blockIdx.x >> 7;
    const int y   = blockIdx.x & 127;

    const int wid = tid >> 5, l = tid & 31;
    const int mrow0 = (wid & 3) * 32;
    const int ncol0 = (wid >> 2) * 32;
    const uint32_t frag_off = (uint32_t)(l & 15) * 144 + (uint32_t)(l >> 4) * 16;

    if (tid < 128) {
        int buf  = tid >> 6;
        int rem  = tid & 63;
        int slot = (rem >= 32) ? 129 : 0;
        int c    = rem & 31;
        *(uint32_t*)(sm + XBUF(buf) + slot * 144 + c * 4) = 0u;
    }

    float acc[2][4][4];
#pragma unroll
    for (int mt = 0; mt < 2; ++mt)
#pragma unroll
        for (int nt = 0; nt < 4; ++nt)
#pragma unroll
            for (int j = 0; j < 4; ++j) acc[mt][nt][j] = 0.f;

    issue_xrow(sbase + XBUF(0), sm, XBUF(0), b, y - 1, tid);
    issue_w(sbase + WBUF(0), 0, tid);
    CP_COMMIT();
    issue_xrow(sbase + XBUF(1), sm, XBUF(1), b, y, tid);
    issue_w(sbase + WBUF(1), 1, tid);
    CP_COMMIT();

    for (int t = 0; t < 9; ++t) {
        const int ky = (t >= 6) ? 2 : (t >= 3 ? 1 : 0);
        const int kx = t - 3 * ky;
        CP_WAIT1();
        __syncthreads();

        const uint32_t aB = sbase + WBUF(t & 1) + (uint32_t)mrow0 * 144 + frag_off;
        const uint32_t bB = sbase + XBUF(ky & 1) + (uint32_t)(kx + ncol0) * 144 + frag_off;

#pragma unroll
        for (int kk = 0; kk < 4; ++kk) {
            uint32_t a[8];
#pragma unroll
            for (int mtt = 0; mtt < 2; ++mtt)
                ldmx4(aB + (uint32_t)mtt * 16 * 144 + kk * 32,
                      a[mtt * 4 + 0], a[mtt * 4 + 1], a[mtt * 4 + 2], a[mtt * 4 + 3]);
            uint32_t bf[4][2];
#pragma unroll
            for (int nb = 0; nb < 2; ++nb) {
                uint32_t r0, r1, r2, r3;
                ldmx4(bB + (uint32_t)nb * 16 * 144 + kk * 32, r0, r1, r2, r3);
                bf[nb * 2 + 0][0] = r0; bf[nb * 2 + 0][1] = r2;
                bf[nb * 2 + 1][0] = r1; bf[nb * 2 + 1][1] = r3;
            }
#pragma unroll
            for (int mt = 0; mt < 2; ++mt)
#pragma unroll
                for (int nt = 0; nt < 4; ++nt)
                    mma16816(acc[mt][nt], a + mt * 4, bf[nt][0], bf[nt][1]);
        }
        __syncthreads();
        if (t < 8) {
            if (t + 2 <= 8) issue_w(sbase + WBUF(t & 1), t + 2, tid);
            if (t == 3)     issue_xrow(sbase + XBUF(0), sm, XBUF(0), b, y + 1, tid);
            CP_COMMIT();
        }
    }

    __half* yb = g_y + (size_t)b * COUT * H_ * W_;
#pragma unroll
    for (int mt = 0; mt < 2; ++mt) {
#pragma unroll
        for (int nt = 0; nt < 4; ++nt) {
            int r   = mrow0 + mt * 16 + (l >> 2);
            int col = ncol0 + nt * 8 + (l & 3) * 2;
            *(__half2*)&yb[((size_t)r * H_ + y) * W_ + col]
                = __floats2half2_rn(acc[mt][nt][0], acc[mt][nt][1]);
            *(__half2*)&yb[((size_t)(r + 8) * H_ + y) * W_ + col]
                = __floats2half2_rn(acc[mt][nt][2], acc[mt][nt][3]);
        }
    }
}

// ---------------- Stage 2+3 fused: dwconv4x4 + silu + head matmul (R12, 63us) ----
#define XS_BYTES   ((128 * 136 + 16) * 2)          // 34848
#define XH_OFF     XS_BYTES
#define WSM_OFF    (XH_OFF + 17192 * 2)            // 69232
#define DW_SM_TOTAL (WSM_OFF + 32 * 80)            // 71792 -> 3 CTAs/SM

__global__ __launch_bounds__(512, 3)
void dwhead_kernel(const float* __restrict__ Wc, const float* __restrict__ bc,
                   const float* __restrict__ W_out, float* __restrict__ out) {
    extern __shared__ char sm[];
    __half* Xs  = (__half*)sm;
    __half* xh  = (__half*)(sm + XH_OFF);
    __half* Wsm = (__half*)(sm + WSM_OFF);

    const int tid = threadIdx.x;
    const int P   = blockIdx.x;
    const int c   = P & 127;
    const int lane = tid & 31, wid = tid >> 5;

    const long base    = (long)P * PLANE;
    const int g_start  = (int)((base + 31) >> 5);
    const int g_end    = (int)((base + PLANE + 31) >> 5);
    const int s0       = (int)((long)g_start * 32 - base);
    const int n_groups = g_end - g_start;
    const int n_k      = n_groups * 32;

    float w[16];
#pragma unroll
    for (int i = 0; i < 16; ++i) w[i] = Wc[c * 16 + i];
    const float bias = bc[c];

    for (int i = tid; i < 1024; i += 512) {
        int e = i >> 5, d = i & 31;
        Wsm[e * 40 + d] = __float2half(W_out[i]);
    }

    const uint4* gy4 = (const uint4*)(g_y + (size_t)P * (H_ * W_));
#pragma unroll
    for (int i = 0; i < 4; ++i) {
        int idx = tid + i * 512;
        uint4 v = gy4[idx];
        int r  = idx >> 4;
        int c8 = (idx & 15) * 8;
        __half* dst = &Xs[r * 136 + 3 + c8];
        const __half* sv = (const __half*)&v;
#pragma unroll
        for (int t2 = 0; t2 < 8; ++t2) dst[t2] = sv[t2];
    }
    for (int idx = tid; idx < 1024; idx += 512) {
        int r = idx >> 3, cc = idx & 7;
        int col = (cc < 3) ? cc : (128 + cc);
        Xs[r * 136 + col] = __float2half(0.f);
    }
    if (tid < 16) Xs[128 * 136 + tid] = __float2half(0.f);
    __syncthreads();

    const int nitem = HO * 33;
    for (int it = tid; it < nitem; it += 512) {
        int y  = it / 33;
        int j  = it - y * 33;
        int x0 = j * 4;
        float a[4] = { bias, bias, bias, bias };
#pragma unroll
        for (int ky = 0; ky < 4; ++ky) {
            int r = y - 3 + ky;
            if ((unsigned)r < 128u) {
                const __half* xr = &Xs[r * 136 + x0];
                uint2 qa = *(const uint2*)xr;
                uint2 qb = *(const uint2*)(xr + 4);
                float2 f0 = __half22float2(*(__half2*)&qa.x);
                float2 f1 = __half22float2(*(__half2*)&qa.y);
                float2 f2 = __half22float2(*(__half2*)&qb.x);
                float2 f3 = __half22float2(*(__half2*)&qb.y);
                float xv[8] = { f0.x, f0.y, f1.x, f1.y, f2.x, f2.y, f3.x, f3.y };
                const float* wk = w + ky * 4;
#pragma unroll
                for (int o = 0; o < 4; ++o)
#pragma unroll
                    for (int kx = 0; kx < 4; ++kx)
                        a[o] += xv[o + kx] * wk[kx];
            }
        }
#pragma unroll
        for (int o = 0; o < 4; ++o) {
            int x = x0 + o;
            if (x < WO) {
                int k = y * WO + x - s0;
                if (k >= 0) xh[k] = __float2half(fast_silu(a[o]));
            }
        }
    }

    if (P < NPLANES - 1 && tid < 31) {
        int i = tid;
        int k = PLANE + i - s0;
        if (k < n_k) {
            int cn = (P + 1) & 127;
            float acc = bc[cn];
            const __half* gp = g_y + (size_t)(P + 1) * (H_ * W_);
#pragma unroll
            for (int kx = 0; kx < 4; ++kx) {
                int ci = i - 3 + kx;
                if (ci >= 0) acc += __half2float(gp[ci]) * Wc[cn * 16 + 12 + kx];
            }
            xh[k] = __float2half(fast_silu(acc));
        }
    }
    __syncthreads();

    const uint32_t wb = smem_u32(Wsm);
    const uint32_t xb = smem_u32(xh);
    const uint32_t foW = (uint32_t)(lane & 15) * 80 + (uint32_t)(lane >> 4) * 16;
    const uint32_t foX = (uint32_t)(lane & 15) * 64 + (uint32_t)(lane >> 4) * 16;
    const int n_tiles = (n_groups + 15) >> 4;

#pragma unroll
    for (int mt = 0; mt < 2; ++mt) {
        uint32_t afr[2][4];
#pragma unroll
        for (int kk = 0; kk < 2; ++kk)
            ldmx4(wb + (uint32_t)mt * 16 * 80 + kk * 32 + foW,
                  afr[kk][0], afr[kk][1], afr[kk][2], afr[kk][3]);

        for (int j = wid; j < n_tiles; j += 16) {
            uint32_t tb = xb + (uint32_t)j * 16 * 64 + foX;
            uint32_t b0[2][2], b1[2][2];
            {
                uint32_t r0, r1, r2, r3;
                ldmx4(tb,      r0, r1, r2, r3);
                b0[0][0] = r0; b0[0][1] = r2;
                b0[1][0] = r1; b0[1][1] = r3;
                ldmx4(tb + 32, r0, r1, r2, r3);
                b1[0][0] = r0; b1[0][1] = r2;
                b1[1][0] = r1; b1[1][1] = r3;
            }
#pragma unroll
            for (int nt = 0; nt < 2; ++nt) {
                float cfr[4] = { 0.f, 0.f, 0.f, 0.f };
                mma16816(cfr, afr[0], b0[nt][0], b0[nt][1]);
                mma16816(cfr, afr[1], b1[nt][0], b1[nt][1]);
                int e  = mt * 16 + (lane >> 2);
                int g0 = j * 16 + nt * 8 + (lane & 3) * 2;
                if (g0 < n_groups) {
                    float* o = out + (size_t)(g_start + g0) * 32;
                    o[e]     = cfr[0];
                    o[e + 8] = cfr[2];
                }
                if (g0 + 1 < n_groups) {
                    float* o = out + (size_t)(g_start + g0 + 1) * 32;
                    o[e]     = cfr[1];
                    o[e + 8] = cfr[3];
                }
            }
        }
    }
}

// ---------------- launch ----------------
extern "C" void kernel_launch(void* const* d_in, const int* in_sizes, int n_in,
                              void* d_out, int out_size) {
    const float* x      = (const float*)d_in[0];
    const float* W_in   = (const float*)d_in[1];
    const float* W_conv = (const float*)d_in[2];
    const float* b_conv = (const float*)d_in[3];
    const float* W_out  = (const float*)d_in[7];
    float* out = (float*)d_out;

    cudaFuncSetAttribute(conv3x3_mma_kernel,
                         cudaFuncAttributeMaxDynamicSharedMemorySize, SM_TOTAL);
    cudaFuncSetAttribute(dwhead_kernel,
                         cudaFuncAttributeMaxDynamicSharedMemorySize, DW_SM_TOTAL);

    prep_x_kernel<<<dim3(H_, B_), 256>>>(x, W_in);
    conv3x3_mma_kernel<<<B_ * H_, 512, SM_TOTAL>>>();
    dwhead_kernel<<<NPLANES, 512, DW_SM_TOTAL>>>(W_conv, b_conv, W_out, out);
}